// round 10
// baseline (speedup 1.0000x reference)
#include <cuda_runtime.h>

// IndRNN recurrence: h_t = relu(h_{t-1} * w[h] + x[t,b,h]), out[t,b,h] = h_t
// x: [T, B, H] fp32, w: [H], h0: [B, H], out: [T, B, H]. T=1024, B=64, H=1024.
// R9: best config (float2, 32-thread blocks, __ldcs/__stcs; 84.0us, ~78% DRAM)
// with PF deepened 32 -> 64. R5's win confounded request-size with PF 16->32;
// this isolates queue depth: 16 KB in flight per warp (16 MB chip) gives the
// DRAM controller maximal reordering freedom to close the 22% idle-cycle gap.
// Regs ~160 — occupancy is grid-bound (1024 CTAs), so deeper buffers are free.

#define T_STEPS 1024
#define B_DIM 64
#define H_DIM 1024
#define BH (B_DIM * H_DIM)
#define BH2 (BH / 2)      // float2 elements per time step
#define H2 (H_DIM / 2)
#define PF 64

__global__ __launch_bounds__(32)
void indrnn_kernel(const float2* __restrict__ x,
                   const float2* __restrict__ w,
                   const float2* __restrict__ h0,
                   float2* __restrict__ out) {
    const int idx = blockIdx.x * blockDim.x + threadIdx.x;  // 0 .. BH2-1
    const int hcol = idx & (H2 - 1);

    const float2 wv = w[hcol];
    float2 h = h0[idx];

    const float2* xp = x + idx;
    float2* op = out + idx;

    float2 buf[PF];

    // Prologue: fill the ring with steps 0..PF-1
    #pragma unroll
    for (int i = 0; i < PF; i++)
        buf[i] = __ldcs(xp + i * BH2);

    const float2* xpre = xp + PF * BH2;

    // Steady state: consume slot i, immediately refill with step t+PF+i.
    #pragma unroll 1
    for (int t = 0; t < T_STEPS - PF; t += PF) {
        #pragma unroll
        for (int i = 0; i < PF; i++) {
            const float2 xv = buf[i];
            buf[i] = __ldcs(xpre + i * BH2);     // prefetch t+PF+i
            h.x = fmaxf(fmaf(h.x, wv.x, xv.x), 0.0f);
            h.y = fmaxf(fmaf(h.y, wv.y, xv.y), 0.0f);
            __stcs(op + i * BH2, h);
        }
        xpre += PF * BH2;
        op   += PF * BH2;
    }

    // Epilogue: last PF steps, ring already full
    #pragma unroll
    for (int i = 0; i < PF; i++) {
        const float2 xv = buf[i];
        h.x = fmaxf(fmaf(h.x, wv.x, xv.x), 0.0f);
        h.y = fmaxf(fmaf(h.y, wv.y, xv.y), 0.0f);
        __stcs(op + i * BH2, h);
    }
}

extern "C" void kernel_launch(void* const* d_in, const int* in_sizes, int n_in,
                              void* d_out, int out_size) {
    const float2* x  = (const float2*)d_in[0];   // [T, B, H]
    const float2* w  = (const float2*)d_in[1];   // [H]
    const float2* h0 = (const float2*)d_in[2];   // [B, H]
    float2* out = (float2*)d_out;                // [T, B, H]

    const int threads = 32;
    const int blocks = BH2 / threads;            // 1024 blocks
    indrnn_kernel<<<blocks, threads>>>(x, w, h0, out);
}

// round 11
// speedup vs baseline: 1.0210x; 1.0210x over previous
#include <cuda_runtime.h>

// IndRNN recurrence: h_t = relu(h_{t-1} * w[h] + x[t,b,h]), out[t,b,h] = h_t
// x: [T, B, H] fp32, w: [H], h0: [B, H], out: [T, B, H]. T=1024, B=64, H=1024.
// R10: R8 base (float2, 32-thread blocks, PF=32 ring, __ldcs/__stcs — best
// 84.0us, 78% DRAM) + prefetch.global.L2 one full ring ahead (t+2*PF).
// The LDG then hits L2 instead of DRAM, and the DRAM controller receives the
// read stream early and steadily, letting it fill read/write turnaround gaps.
// (R9 falsified deeper rings: PF=64 flat in-kernel, worse wallclock.)

#define T_STEPS 1024
#define B_DIM 64
#define H_DIM 1024
#define BH (B_DIM * H_DIM)
#define BH2 (BH / 2)      // float2 elements per time step
#define H2 (H_DIM / 2)
#define PF 32

__global__ __launch_bounds__(32)
void indrnn_kernel(const float2* __restrict__ x,
                   const float2* __restrict__ w,
                   const float2* __restrict__ h0,
                   float2* __restrict__ out) {
    const int idx = blockIdx.x * blockDim.x + threadIdx.x;  // 0 .. BH2-1
    const int hcol = idx & (H2 - 1);

    const float2 wv = w[hcol];
    float2 h = h0[idx];

    const float2* xp = x + idx;
    float2* op = out + idx;

    float2 buf[PF];

    // Prologue: fill the ring with steps 0..PF-1, and pre-warm L2 for the
    // next ring (PF..2PF-1) so steady-state LDGs land on L2 hits.
    #pragma unroll
    for (int i = 0; i < PF; i++) {
        buf[i] = __ldcs(xp + i * BH2);
        asm volatile("prefetch.global.L2 [%0];" :: "l"(xp + (PF + i) * BH2));
    }

    const float2* xpre = xp + PF * BH2;

    // Steady state: consume slot i, refill it (L2 hit thanks to the earlier
    // prefetch), and prefetch one full ring further ahead into L2.
    #pragma unroll 1
    for (int t = 0; t < T_STEPS - PF; t += PF) {
        const int remaining = T_STEPS - PF - t;  // steps left after this ring
        #pragma unroll
        for (int i = 0; i < PF; i++) {
            const float2 xv = buf[i];
            buf[i] = __ldcs(xpre + i * BH2);     // fetch t+PF+i (L2-resident)
            if (remaining > PF)                   // prefetch t+2*PF+i into L2
                asm volatile("prefetch.global.L2 [%0];"
                             :: "l"(xpre + (PF + i) * BH2));
            h.x = fmaxf(fmaf(h.x, wv.x, xv.x), 0.0f);
            h.y = fmaxf(fmaf(h.y, wv.y, xv.y), 0.0f);
            __stcs(op + i * BH2, h);
        }
        xpre += PF * BH2;
        op   += PF * BH2;
    }

    // Epilogue: last PF steps, ring already full
    #pragma unroll
    for (int i = 0; i < PF; i++) {
        const float2 xv = buf[i];
        h.x = fmaxf(fmaf(h.x, wv.x, xv.x), 0.0f);
        h.y = fmaxf(fmaf(h.y, wv.y, xv.y), 0.0f);
        __stcs(op + i * BH2, h);
    }
}

extern "C" void kernel_launch(void* const* d_in, const int* in_sizes, int n_in,
                              void* d_out, int out_size) {
    const float2* x  = (const float2*)d_in[0];   // [T, B, H]
    const float2* w  = (const float2*)d_in[1];   // [H]
    const float2* h0 = (const float2*)d_in[2];   // [B, H]
    float2* out = (float2*)d_out;                // [T, B, H]

    const int threads = 32;
    const int blocks = BH2 / threads;            // 1024 blocks
    indrnn_kernel<<<blocks, threads>>>(x, w, h0, out);
}

// round 12
// speedup vs baseline: 1.0489x; 1.0274x over previous
#include <cuda_runtime.h>

// IndRNN recurrence: h_t = relu(h_{t-1} * w[h] + x[t,b,h]), out[t,b,h] = h_t
// x: [T, B, H] fp32, w: [H], h0: [B, H], out: [T, B, H]. T=1024, B=64, H=1024.
// R11: phase-batched double buffer at float2 (the R2 experiment, un-sabotaged:
// R2 ran under a 32-reg cap that made the buffers impossible). Per warp:
// 32 back-to-back LDG.64 (8 KB read burst), then 32 FFMA+STG.64 (8 KB write
// burst) — 32x longer same-direction DRAM streaks vs the ld/st-alternating
// R8 ring, attacking the 22% DRAM idle (turnaround) directly. Loads for the
// next chunk always precede compute of the current chunk (latency unchanged).
// (R10 falsified L2 prefetch: doubled LTS request traffic, DRAM% fell.)

#define T_STEPS 1024
#define B_DIM 64
#define H_DIM 1024
#define BH (B_DIM * H_DIM)
#define BH2 (BH / 2)      // float2 elements per time step
#define H2 (H_DIM / 2)
#define CH 32             // chunk of time steps per phase

__global__ __launch_bounds__(32)
void indrnn_kernel(const float2* __restrict__ x,
                   const float2* __restrict__ w,
                   const float2* __restrict__ h0,
                   float2* __restrict__ out) {
    const int idx = blockIdx.x * blockDim.x + threadIdx.x;  // 0 .. BH2-1
    const int hcol = idx & (H2 - 1);

    const float2 wv = w[hcol];
    float2 h = h0[idx];

    const float2* xp = x + idx;
    float2* op = out + idx;

    float2 bufA[CH], bufB[CH];

    // Prologue: load chunk 0 into A (8 KB read burst per warp)
    #pragma unroll
    for (int i = 0; i < CH; i++)
        bufA[i] = __ldcs(xp + i * BH2);

    // Steady state: 2 chunks per iteration; each compute phase is preceded
    // by the load phase of the following chunk.
    #pragma unroll 1
    for (int t = 0; t < T_STEPS - 2 * CH; t += 2 * CH) {
        const float2* xb = xp + (t + CH) * BH2;
        #pragma unroll
        for (int i = 0; i < CH; i++)             // read burst: chunk t+CH
            bufB[i] = __ldcs(xb + i * BH2);
        float2* oa = op + t * BH2;
        #pragma unroll
        for (int i = 0; i < CH; i++) {           // write burst: chunk t
            h.x = fmaxf(fmaf(h.x, wv.x, bufA[i].x), 0.0f);
            h.y = fmaxf(fmaf(h.y, wv.y, bufA[i].y), 0.0f);
            __stcs(oa + i * BH2, h);
        }
        const float2* xa = xp + (t + 2 * CH) * BH2;
        #pragma unroll
        for (int i = 0; i < CH; i++)             // read burst: chunk t+2CH
            bufA[i] = __ldcs(xa + i * BH2);
        float2* ob = op + (t + CH) * BH2;
        #pragma unroll
        for (int i = 0; i < CH; i++) {           // write burst: chunk t+CH
            h.x = fmaxf(fmaf(h.x, wv.x, bufB[i].x), 0.0f);
            h.y = fmaxf(fmaf(h.y, wv.y, bufB[i].y), 0.0f);
            __stcs(ob + i * BH2, h);
        }
    }

    // Epilogue: last two chunks (A loaded; load B, then compute both)
    {
        const int t = T_STEPS - 2 * CH;
        const float2* xb = xp + (t + CH) * BH2;
        #pragma unroll
        for (int i = 0; i < CH; i++)
            bufB[i] = __ldcs(xb + i * BH2);
        float2* oa = op + t * BH2;
        #pragma unroll
        for (int i = 0; i < CH; i++) {
            h.x = fmaxf(fmaf(h.x, wv.x, bufA[i].x), 0.0f);
            h.y = fmaxf(fmaf(h.y, wv.y, bufA[i].y), 0.0f);
            __stcs(oa + i * BH2, h);
        }
        float2* ob = op + (t + CH) * BH2;
        #pragma unroll
        for (int i = 0; i < CH; i++) {
            h.x = fmaxf(fmaf(h.x, wv.x, bufB[i].x), 0.0f);
            h.y = fmaxf(fmaf(h.y, wv.y, bufB[i].y), 0.0f);
            __stcs(ob + i * BH2, h);
        }
    }
}

extern "C" void kernel_launch(void* const* d_in, const int* in_sizes, int n_in,
                              void* d_out, int out_size) {
    const float2* x  = (const float2*)d_in[0];   // [T, B, H]
    const float2* w  = (const float2*)d_in[1];   // [H]
    const float2* h0 = (const float2*)d_in[2];   // [B, H]
    float2* out = (float2*)d_out;                // [T, B, H]

    const int threads = 32;
    const int blocks = BH2 / threads;            // 1024 blocks
    indrnn_kernel<<<blocks, threads>>>(x, w, h0, out);
}

// round 13
// speedup vs baseline: 1.0640x; 1.0144x over previous
#include <cuda_runtime.h>

// IndRNN recurrence: h_t = relu(h_{t-1} * w[h] + x[t,b,h]), out[t,b,h] = h_t
// x: [T, B, H] fp32, w: [H], h0: [B, H], out: [T, B, H]. T=1024, B=64, H=1024.
// R12: R8 base (float2, 32-thread blocks, PF=32 rotating ring — best wallclock
// 84.0us), single change: stores use DEFAULT write-back policy instead of
// __stcs. Loads keep __ldcs (read-once, evict-first: the proven R5 lever).
// Model conclusion from R1-R11: all variants pin at ~6.3 TB/s = the B300 LTS
// throughput cap (path-independent) — in-kernel time is at the roofline;
// only store policy / tail effects remain as wallclock variables.

#define T_STEPS 1024
#define B_DIM 64
#define H_DIM 1024
#define BH (B_DIM * H_DIM)
#define BH2 (BH / 2)      // float2 elements per time step
#define H2 (H_DIM / 2)
#define PF 32

__global__ __launch_bounds__(32)
void indrnn_kernel(const float2* __restrict__ x,
                   const float2* __restrict__ w,
                   const float2* __restrict__ h0,
                   float2* __restrict__ out) {
    const int idx = blockIdx.x * blockDim.x + threadIdx.x;  // 0 .. BH2-1
    const int hcol = idx & (H2 - 1);

    const float2 wv = w[hcol];
    float2 h = h0[idx];

    const float2* xp = x + idx;
    float2* op = out + idx;

    float2 buf[PF];

    // Prologue: fill the ring with steps 0..PF-1
    #pragma unroll
    for (int i = 0; i < PF; i++)
        buf[i] = __ldcs(xp + i * BH2);

    const float2* xpre = xp + PF * BH2;

    // Steady state: consume slot i, immediately refill with step t+PF+i.
    #pragma unroll 1
    for (int t = 0; t < T_STEPS - PF; t += PF) {
        #pragma unroll
        for (int i = 0; i < PF; i++) {
            const float2 xv = buf[i];
            buf[i] = __ldcs(xpre + i * BH2);     // prefetch t+PF+i
            h.x = fmaxf(fmaf(h.x, wv.x, xv.x), 0.0f);
            h.y = fmaxf(fmaf(h.y, wv.y, xv.y), 0.0f);
            op[i * BH2] = h;                     // default write-back store
        }
        xpre += PF * BH2;
        op   += PF * BH2;
    }

    // Epilogue: last PF steps, ring already full
    #pragma unroll
    for (int i = 0; i < PF; i++) {
        const float2 xv = buf[i];
        h.x = fmaxf(fmaf(h.x, wv.x, xv.x), 0.0f);
        h.y = fmaxf(fmaf(h.y, wv.y, xv.y), 0.0f);
        op[i * BH2] = h;
    }
}

extern "C" void kernel_launch(void* const* d_in, const int* in_sizes, int n_in,
                              void* d_out, int out_size) {
    const float2* x  = (const float2*)d_in[0];   // [T, B, H]
    const float2* w  = (const float2*)d_in[1];   // [H]
    const float2* h0 = (const float2*)d_in[2];   // [B, H]
    float2* out = (float2*)d_out;                // [T, B, H]

    const int threads = 32;
    const int blocks = BH2 / threads;            // 1024 blocks
    indrnn_kernel<<<blocks, threads>>>(x, w, h0, out);
}

// round 14
// speedup vs baseline: 1.0944x; 1.0285x over previous
#include <cuda_runtime.h>

// IndRNN recurrence: h_t = relu(h_{t-1} * w[h] + x[t,b,h]), out[t,b,h] = h_t
// x: [T, B, H] fp32, w: [H], h0: [B, H], out: [T, B, H]. T=1024, B=64, H=1024.
//
// FINAL (R8 config, measured best 84.0us wallclock / 78.75us in-kernel):
//   - float2 per thread (32768 threads): LDG.64/STG.64, the request-size
//     sweet spot (float1 is request-rate-capped at 67% DRAM; float4 starves
//     warp count and regressed).
//   - __ldcs loads (read-once, evict-first) + __stcs stores (minimize dirty-
//     L2 carryover between graph replays). R7/R12 falsified __stwt/default.
//   - PF=32 rotating prefetch ring: ~8 KB continuously in flight per warp,
//     well above the BW*latency product. R9 falsified deeper (PF=64).
//   - 32-thread blocks -> 1024 CTAs / 148 SMs (balanced wave, max 7 vs 6.92).
//
// Roofline: all structural variants (R1-R12) pin at 6.0-6.3 TB/s = the B300
// LTS throughput cap (~6300 B/cyc, path-independent). The 512 MB of traffic
// is irreducible (ReLU breaks scan linearity), so in-kernel time is at the
// memory-system roofline; remaining wallclock spread is replay/tail noise.

#define T_STEPS 1024
#define B_DIM 64
#define H_DIM 1024
#define BH (B_DIM * H_DIM)
#define BH2 (BH / 2)      // float2 elements per time step
#define H2 (H_DIM / 2)
#define PF 32

__global__ __launch_bounds__(32)
void indrnn_kernel(const float2* __restrict__ x,
                   const float2* __restrict__ w,
                   const float2* __restrict__ h0,
                   float2* __restrict__ out) {
    const int idx = blockIdx.x * blockDim.x + threadIdx.x;  // 0 .. BH2-1
    const int hcol = idx & (H2 - 1);

    const float2 wv = w[hcol];
    float2 h = h0[idx];

    const float2* xp = x + idx;
    float2* op = out + idx;

    float2 buf[PF];

    // Prologue: fill the ring with steps 0..PF-1
    #pragma unroll
    for (int i = 0; i < PF; i++)
        buf[i] = __ldcs(xp + i * BH2);

    const float2* xpre = xp + PF * BH2;

    // Steady state: consume slot i, immediately refill with step t+PF+i.
    // Refill loads are independent of the recurrence chain, so ~32 LDG.64
    // stay continuously in flight per warp.
    #pragma unroll 1
    for (int t = 0; t < T_STEPS - PF; t += PF) {
        #pragma unroll
        for (int i = 0; i < PF; i++) {
            const float2 xv = buf[i];
            buf[i] = __ldcs(xpre + i * BH2);     // prefetch t+PF+i
            h.x = fmaxf(fmaf(h.x, wv.x, xv.x), 0.0f);
            h.y = fmaxf(fmaf(h.y, wv.y, xv.y), 0.0f);
            __stcs(op + i * BH2, h);
        }
        xpre += PF * BH2;
        op   += PF * BH2;
    }

    // Epilogue: last PF steps, ring already full
    #pragma unroll
    for (int i = 0; i < PF; i++) {
        const float2 xv = buf[i];
        h.x = fmaxf(fmaf(h.x, wv.x, xv.x), 0.0f);
        h.y = fmaxf(fmaf(h.y, wv.y, xv.y), 0.0f);
        __stcs(op + i * BH2, h);
    }
}

extern "C" void kernel_launch(void* const* d_in, const int* in_sizes, int n_in,
                              void* d_out, int out_size) {
    const float2* x  = (const float2*)d_in[0];   // [T, B, H]
    const float2* w  = (const float2*)d_in[1];   // [H]
    const float2* h0 = (const float2*)d_in[2];   // [B, H]
    float2* out = (float2*)d_out;                // [T, B, H]

    const int threads = 32;
    const int blocks = BH2 / threads;            // 1024 blocks -> 6.92 CTAs/SM
    indrnn_kernel<<<blocks, threads>>>(x, w, h0, out);
}